// round 1
// baseline (speedup 1.0000x reference)
#include <cuda_runtime.h>

// NeuralODE dopri5 rollout, fp32 SIMT persistent kernel.
// T=32 times, B=2048 batch, D=64, W=256, N_SUB=2.
// Each CTA owns 16 batch rows and integrates them through all 31 intervals
// (2 substeps each, 6 vf evals per substep). Batch rows are independent, so
// no inter-CTA communication is needed.

#define NT 256
#define MT 16
#define NBLK 128        // 2048 / 16
#define BATCH 2048
#define DIM 64
#define WID 256
#define BD (BATCH*DIM)

// shared memory layout (float offsets)
#define OFF_W0 0            // 256 rows x 68 (padded)   = 17408
#define OFF_W2 17408        // 64 rows x 260 (padded)   = 16640
#define OFF_B0 34048        // 256
#define OFF_B1 34304        // 256
#define OFF_B2 34560        // 64
#define OFF_Y  34624        // 16x64
#define OFF_YS 35648        // 16x64
#define OFF_H1 36672        // 16x256
#define OFF_H2 40768        // 16x256
#define OFF_K  44864        // 6 x 16x64
#define SMEM_FLOATS 51008
#define SMEM_BYTES (SMEM_FLOATS * 4)

// W1 transposed: W1T[k][j] = W1[j][k], so layer-1 weight loads are coalesced
// (thread j reads column j for consecutive k).
__device__ float g_W1T[WID * WID];

__global__ void transpose_w1(const float* __restrict__ w1) {
    int idx = blockIdx.x * blockDim.x + threadIdx.x;   // 0..65535
    int j = idx >> 8;
    int k = idx & 255;
    g_W1T[k * WID + j] = w1[idx];
}

__device__ __forceinline__ float fast_tanhf(float x) {
    // tanh(x) = 1 - 2/(e^{2x}+1); robust at +-inf, accurate to ~1e-6 rel.
    float e = __expf(2.0f * x);
    return 1.0f - __fdividef(2.0f, e + 1.0f);
}

// One vector-field evaluation: reads sYs (16x64), writes kout (16x64).
__device__ __forceinline__ void vf_eval(float* sm, const float* __restrict__ w1t,
                                        float tstage, int tid, float* kout) {
    const int j = tid;

    // ---- layer 0: h1 = tanh(ys @ W0^T + b0), K=64, out 16x256 ----
    {
        float acc[16];
#pragma unroll
        for (int m = 0; m < 16; m++) acc[m] = 0.0f;
        const float4* wr = (const float4*)(sm + OFF_W0 + j * 68);   // 17 float4/row
        const float4* yv = (const float4*)(sm + OFF_YS);            // [m*16 + kk]
#pragma unroll 4
        for (int kk = 0; kk < 16; kk++) {
            float4 w = wr[kk];
#pragma unroll
            for (int m = 0; m < 16; m++) {
                float4 a = yv[m * 16 + kk];
                acc[m] = fmaf(a.x, w.x, acc[m]);
                acc[m] = fmaf(a.y, w.y, acc[m]);
                acc[m] = fmaf(a.z, w.z, acc[m]);
                acc[m] = fmaf(a.w, w.w, acc[m]);
            }
        }
        float b = sm[OFF_B0 + j];
        float* h1 = sm + OFF_H1;
#pragma unroll
        for (int m = 0; m < 16; m++) h1[m * 256 + j] = fast_tanhf(acc[m] + b);
    }
    __syncthreads();

    // ---- layer 1: h2 = tanh(h1 @ W1^T + b1), K=256, out 16x256 ----
    {
        float acc[16];
#pragma unroll
        for (int m = 0; m < 16; m++) acc[m] = 0.0f;
        const float4* hv = (const float4*)(sm + OFF_H1);            // [m*64 + kk]
#pragma unroll 4
        for (int kk = 0; kk < 64; kk++) {
            // coalesced: thread j reads W1T[4kk+q][j]
            float w0 = w1t[(kk * 4 + 0) * WID + j];
            float w1_ = w1t[(kk * 4 + 1) * WID + j];
            float w2_ = w1t[(kk * 4 + 2) * WID + j];
            float w3 = w1t[(kk * 4 + 3) * WID + j];
#pragma unroll
            for (int m = 0; m < 16; m++) {
                float4 a = hv[m * 64 + kk];
                acc[m] = fmaf(a.x, w0, acc[m]);
                acc[m] = fmaf(a.y, w1_, acc[m]);
                acc[m] = fmaf(a.z, w2_, acc[m]);
                acc[m] = fmaf(a.w, w3, acc[m]);
            }
        }
        float b = sm[OFF_B1 + j];
        float* h2 = sm + OFF_H2;
#pragma unroll
        for (int m = 0; m < 16; m++) h2[m * 256 + j] = fast_tanhf(acc[m] + b);
    }
    __syncthreads();

    // ---- layer 2: k = (h2 @ W2^T + b2) * exp(t), K=256, out 16x64 ----
    {
        float et = __expf(tstage);
        int d = tid >> 2;
        int g = tid & 3;
        float acc[4] = {0.f, 0.f, 0.f, 0.f};
        const float4* wr = (const float4*)(sm + OFF_W2 + d * 260);  // 65 float4/row
        const float4* hv = (const float4*)(sm + OFF_H2);            // [m*64 + kk]
#pragma unroll 8
        for (int kk = 0; kk < 64; kk++) {
            float4 w = wr[kk];
#pragma unroll
            for (int r = 0; r < 4; r++) {
                float4 a = hv[(g + 4 * r) * 64 + kk];
                acc[r] = fmaf(a.x, w.x, acc[r]);
                acc[r] = fmaf(a.y, w.y, acc[r]);
                acc[r] = fmaf(a.z, w.z, acc[r]);
                acc[r] = fmaf(a.w, w.w, acc[r]);
            }
        }
        float b = sm[OFF_B2 + d];
#pragma unroll
        for (int r = 0; r < 4; r++) kout[(g + 4 * r) * 64 + d] = (acc[r] + b) * et;
    }
    __syncthreads();
}

__global__ void __launch_bounds__(NT)
node_kernel(const float* __restrict__ ts, const float* __restrict__ y0,
            const float* __restrict__ W0, const float* __restrict__ b0,
            const float* __restrict__ b1, const float* __restrict__ W2,
            const float* __restrict__ b2, float* __restrict__ out) {
    extern __shared__ float sm[];
    const int tid = threadIdx.x;
    const int row0 = blockIdx.x * MT;

    // stage weights into shared (padded rows to kill bank conflicts)
    for (int idx = tid; idx < WID * DIM; idx += NT) {
        int j = idx >> 6, d = idx & 63;
        sm[OFF_W0 + j * 68 + d] = W0[idx];
    }
    for (int idx = tid; idx < DIM * WID; idx += NT) {
        int d = idx >> 8, k = idx & 255;
        sm[OFF_W2 + d * 260 + k] = W2[idx];
    }
    sm[OFF_B0 + tid] = b0[tid];
    sm[OFF_B1 + tid] = b1[tid];
    if (tid < DIM) sm[OFF_B2 + tid] = b2[tid];

    // load y0 tile, write output slab t=0
    for (int idx = tid; idx < MT * DIM; idx += NT) {
        int m = idx >> 6, d = idx & 63;
        float v = y0[(size_t)(row0 + m) * DIM + d];
        sm[OFF_Y + idx] = v;
        out[(size_t)(row0 + m) * DIM + d] = v;
    }
    __syncthreads();

    float* sY = sm + OFF_Y;
    float* sYs = sm + OFF_YS;
    float* k1 = sm + OFF_K + 0 * 1024;
    float* k2 = sm + OFF_K + 1 * 1024;
    float* k3 = sm + OFF_K + 2 * 1024;
    float* k4 = sm + OFF_K + 3 * 1024;
    float* k5 = sm + OFF_K + 4 * 1024;
    float* k6 = sm + OFF_K + 5 * 1024;

    // dopri5 tableau (f32-rounded from exact rationals, matching the reference)
    const float A21 = 0.2f;
    const float A31 = (float)(3.0 / 40.0), A32 = (float)(9.0 / 40.0);
    const float A41 = (float)(44.0 / 45.0), A42 = (float)(-56.0 / 15.0), A43 = (float)(32.0 / 9.0);
    const float A51 = (float)(19372.0 / 6561.0), A52 = (float)(-25360.0 / 2187.0),
                A53 = (float)(64448.0 / 6561.0), A54 = (float)(-212.0 / 729.0);
    const float A61 = (float)(9017.0 / 3168.0), A62 = (float)(-355.0 / 33.0),
                A63 = (float)(46732.0 / 5247.0), A64 = (float)(49.0 / 176.0),
                A65 = (float)(-5103.0 / 18656.0);
    const float BB1 = (float)(35.0 / 384.0), BB3 = (float)(500.0 / 1113.0),
                BB4 = (float)(125.0 / 192.0), BB5 = (float)(-2187.0 / 6784.0),
                BB6 = (float)(11.0 / 84.0);

    for (int iv = 0; iv < 31; iv++) {
        float t0 = ts[iv];
        float dtf = ts[iv + 1] - t0;
        float hh = dtf * 0.5f;
        float tc = t0;

        for (int sub = 0; sub < 2; sub++) {
            // stage 1: ys = y
#pragma unroll
            for (int u = 0; u < 4; u++) { int i = tid + u * NT; sYs[i] = sY[i]; }
            __syncthreads();
            vf_eval(sm, g_W1T, tc, tid, k1);

            // stage 2
#pragma unroll
            for (int u = 0; u < 4; u++) {
                int i = tid + u * NT;
                sYs[i] = fmaf(hh, A21 * k1[i], sY[i]);
            }
            __syncthreads();
            vf_eval(sm, g_W1T, tc + 0.2f * hh, tid, k2);

            // stage 3
#pragma unroll
            for (int u = 0; u < 4; u++) {
                int i = tid + u * NT;
                float s = A31 * k1[i] + A32 * k2[i];
                sYs[i] = fmaf(hh, s, sY[i]);
            }
            __syncthreads();
            vf_eval(sm, g_W1T, tc + 0.3f * hh, tid, k3);

            // stage 4
#pragma unroll
            for (int u = 0; u < 4; u++) {
                int i = tid + u * NT;
                float s = A41 * k1[i] + A42 * k2[i] + A43 * k3[i];
                sYs[i] = fmaf(hh, s, sY[i]);
            }
            __syncthreads();
            vf_eval(sm, g_W1T, tc + 0.8f * hh, tid, k4);

            // stage 5
#pragma unroll
            for (int u = 0; u < 4; u++) {
                int i = tid + u * NT;
                float s = A51 * k1[i] + A52 * k2[i] + A53 * k3[i] + A54 * k4[i];
                sYs[i] = fmaf(hh, s, sY[i]);
            }
            __syncthreads();
            vf_eval(sm, g_W1T, tc + (float)(8.0 / 9.0) * hh, tid, k5);

            // stage 6
#pragma unroll
            for (int u = 0; u < 4; u++) {
                int i = tid + u * NT;
                float s = A61 * k1[i] + A62 * k2[i] + A63 * k3[i] + A64 * k4[i] + A65 * k5[i];
                sYs[i] = fmaf(hh, s, sY[i]);
            }
            __syncthreads();
            vf_eval(sm, g_W1T, tc + hh, tid, k6);

            // final combine (in place on sY)
#pragma unroll
            for (int u = 0; u < 4; u++) {
                int i = tid + u * NT;
                float s = BB1 * k1[i] + BB3 * k3[i] + BB4 * k4[i] + BB5 * k5[i] + BB6 * k6[i];
                sY[i] = fmaf(hh, s, sY[i]);
            }
            __syncthreads();
            tc += hh;
        }

        // write output slab t = iv+1
        for (int idx = tid; idx < MT * DIM; idx += NT) {
            int m = idx >> 6, d = idx & 63;
            out[(size_t)(iv + 1) * BD + (size_t)(row0 + m) * DIM + d] = sm[OFF_Y + idx];
        }
        __syncthreads();
    }
}

extern "C" void kernel_launch(void* const* d_in, const int* in_sizes, int n_in,
                              void* d_out, int out_size) {
    const float* ts = (const float*)d_in[0];
    const float* y0 = (const float*)d_in[1];
    const float* W0 = (const float*)d_in[2];
    const float* b0 = (const float*)d_in[3];
    const float* W1 = (const float*)d_in[4];
    const float* b1 = (const float*)d_in[5];
    const float* W2 = (const float*)d_in[6];
    const float* b2 = (const float*)d_in[7];
    float* out = (float*)d_out;

    cudaFuncSetAttribute(node_kernel, cudaFuncAttributeMaxDynamicSharedMemorySize,
                         SMEM_BYTES);

    transpose_w1<<<WID * WID / 256, 256>>>(W1);
    node_kernel<<<NBLK, NT, SMEM_BYTES>>>(ts, y0, W0, b0, b1, W2, b2, out);
}

// round 2
// speedup vs baseline: 2.0755x; 2.0755x over previous
#include <cuda_runtime.h>

// NeuralODE dopri5 rollout — fp32x2 packed SIMT persistent kernel.
// Pairs batch rows (p, p+8) into 64-bit lanes for fma.rn.f32x2 (FFMA2).
// Activations stored paired: [pair p][col k] = {x[p][k], x[p+8][k]}.

#define NT 256
#define MT 16
#define NBLK 128
#define DIM 64
#define WID 256
#define BD (2048*64)

// shared memory layout (float offsets)
#define OFF_W0 0            // 256 x 68 (pad)  = 17408
#define OFF_W2 17408        // 64 x 262 (pad)  = 16768
#define OFF_B0 34176
#define OFF_B1 34432
#define OFF_B2 34688
#define OFF_Y  34752        // paired [8][64] float2 = 1024 floats
#define OFF_YS 35776        // 1024
#define OFF_H1 36800        // paired [8][256] float2 = 4096
#define OFF_H2 40896        // 4096
#define OFF_K  44992        // 6 x 1024
#define SMEM_FLOATS 51136
#define SMEM_BYTES (SMEM_FLOATS * 4)

typedef unsigned long long u64;

__device__ float g_W1T[WID * WID];   // W1T[k][j] = W1[j][k]

__global__ void transpose_w1(const float* __restrict__ w1) {
    int idx = blockIdx.x * 256 + threadIdx.x;
    int j = idx >> 8;
    int k = idx & 255;
    g_W1T[k * WID + j] = w1[idx];
}

__device__ __forceinline__ u64 pack2(float w) {
    u64 r; unsigned u = __float_as_uint(w);
    asm("mov.b64 %0, {%1, %1};" : "=l"(r) : "r"(u));
    return r;
}
__device__ __forceinline__ u64 pack2f(float a, float b) {
    u64 r;
    asm("mov.b64 %0, {%1, %2};" : "=l"(r) : "r"(__float_as_uint(a)), "r"(__float_as_uint(b)));
    return r;
}
__device__ __forceinline__ void fma2(u64& d, u64 a, u64 b) {
    asm("fma.rn.f32x2 %0, %1, %2, %0;" : "+l"(d) : "l"(a), "l"(b));
}
__device__ __forceinline__ float lo32(u64 v) { return __uint_as_float((unsigned)v); }
__device__ __forceinline__ float hi32(u64 v) { return __uint_as_float((unsigned)(v >> 32)); }

__device__ __forceinline__ float fast_tanhf(float x) {
    float e = __expf(2.0f * x);
    return 1.0f - __fdividef(2.0f, e + 1.0f);
}

// One vf eval + inline stage combine.
// ysSrc: paired activation input [8][64]. kOut: paired k output [8][64].
// After computing k, builds ysOut = y + hh*(c1*k1+..+c5*k5 + ccur*k_current).
__device__ __noinline__ void vf_eval(float* sm, const float* __restrict__ w1t,
                                     float tstage, int tid,
                                     const float* ysSrc, float* kOut,
                                     float hh, float c1, float c2, float c3,
                                     float c4, float c5, float ccur,
                                     float* ysOut) {
    const int j = tid;

    // ---- layer 0: h1 = tanh(ys @ W0^T + b0), K=64 ----
    {
        u64 acc[8];
#pragma unroll
        for (int p = 0; p < 8; p++) acc[p] = 0ull;
        const float4* w4 = (const float4*)(sm + OFF_W0 + j * 68);
        const ulonglong2* a2 = (const ulonglong2*)ysSrc;
#pragma unroll 4
        for (int kk = 0; kk < 16; kk++) {
            float4 w = w4[kk];
            u64 wd0 = pack2(w.x), wd1 = pack2(w.y), wd2 = pack2(w.z), wd3 = pack2(w.w);
#pragma unroll
            for (int p = 0; p < 8; p++) {
                ulonglong2 x0 = a2[p * 32 + kk * 2];
                ulonglong2 x1 = a2[p * 32 + kk * 2 + 1];
                fma2(acc[p], x0.x, wd0);
                fma2(acc[p], x0.y, wd1);
                fma2(acc[p], x1.x, wd2);
                fma2(acc[p], x1.y, wd3);
            }
        }
        float b = sm[OFF_B0 + j];
        u64* h1u = (u64*)(sm + OFF_H1);
#pragma unroll
        for (int p = 0; p < 8; p++) {
            float tl = fast_tanhf(lo32(acc[p]) + b);
            float th = fast_tanhf(hi32(acc[p]) + b);
            h1u[p * 256 + j] = pack2f(tl, th);
        }
    }
    __syncthreads();

    // ---- layer 1: h2 = tanh(h1 @ W1^T + b1), K=256 (W1T from global) ----
    {
        u64 acc[8];
#pragma unroll
        for (int p = 0; p < 8; p++) acc[p] = 0ull;
        const ulonglong2* h2a = (const ulonglong2*)(sm + OFF_H1);
        const float* wp = w1t + j;
#pragma unroll 2
        for (int kk = 0; kk < 64; kk++) {
            float w0f = wp[(4 * kk + 0) * WID];
            float w1f = wp[(4 * kk + 1) * WID];
            float w2f = wp[(4 * kk + 2) * WID];
            float w3f = wp[(4 * kk + 3) * WID];
            u64 wd0 = pack2(w0f), wd1 = pack2(w1f), wd2 = pack2(w2f), wd3 = pack2(w3f);
#pragma unroll
            for (int p = 0; p < 8; p++) {
                ulonglong2 x0 = h2a[p * 128 + kk * 2];
                ulonglong2 x1 = h2a[p * 128 + kk * 2 + 1];
                fma2(acc[p], x0.x, wd0);
                fma2(acc[p], x0.y, wd1);
                fma2(acc[p], x1.x, wd2);
                fma2(acc[p], x1.y, wd3);
            }
        }
        float b = sm[OFF_B1 + j];
        u64* h2u = (u64*)(sm + OFF_H2);
#pragma unroll
        for (int p = 0; p < 8; p++) {
            float tl = fast_tanhf(lo32(acc[p]) + b);
            float th = fast_tanhf(hi32(acc[p]) + b);
            h2u[p * 256 + j] = pack2f(tl, th);
        }
    }
    __syncthreads();

    // ---- layer 2 + stage combine ----
    {
        const int d = tid & 63;
        const int q = tid >> 6;
        const int p0 = q * 2;
        u64 acc0 = 0ull, acc1 = 0ull;
        const float2* w2p = (const float2*)(sm + OFF_W2 + d * 262);
        const ulonglong2* hv = (const ulonglong2*)(sm + OFF_H2);
#pragma unroll 4
        for (int kk = 0; kk < 64; kk++) {
            float2 wa = w2p[2 * kk];
            float2 wb = w2p[2 * kk + 1];
            u64 wd0 = pack2(wa.x), wd1 = pack2(wa.y), wd2 = pack2(wb.x), wd3 = pack2(wb.y);
            ulonglong2 xa = hv[p0 * 128 + 2 * kk];
            ulonglong2 xb = hv[p0 * 128 + 2 * kk + 1];
            ulonglong2 ya = hv[(p0 + 1) * 128 + 2 * kk];
            ulonglong2 yb = hv[(p0 + 1) * 128 + 2 * kk + 1];
            fma2(acc0, xa.x, wd0); fma2(acc0, xa.y, wd1);
            fma2(acc0, xb.x, wd2); fma2(acc0, xb.y, wd3);
            fma2(acc1, ya.x, wd0); fma2(acc1, ya.y, wd1);
            fma2(acc1, yb.x, wd2); fma2(acc1, yb.y, wd3);
        }
        float et = __expf(tstage);
        float bv = sm[OFF_B2 + d];
        float k0l = (lo32(acc0) + bv) * et;
        float k0h = (hi32(acc0) + bv) * et;
        float k1l = (lo32(acc1) + bv) * et;
        float k1h = (hi32(acc1) + bv) * et;
        u64 kv0 = pack2f(k0l, k0h);
        u64 kv1 = pack2f(k1l, k1h);
        u64* ku = (u64*)kOut;
        ku[p0 * 64 + d] = kv0;
        ku[(p0 + 1) * 64 + d] = kv1;

        // inline combine: ysOut = y + hh*(c1*k1 + ... + c5*k5 + ccur*kcur)
        const u64* k1u = (const u64*)(sm + OFF_K + 0 * 1024);
        const u64* k2u = (const u64*)(sm + OFF_K + 1 * 1024);
        const u64* k3u = (const u64*)(sm + OFF_K + 2 * 1024);
        const u64* k4u = (const u64*)(sm + OFF_K + 3 * 1024);
        const u64* k5u = (const u64*)(sm + OFF_K + 4 * 1024);
        const u64* yu = (const u64*)(sm + OFF_Y);
        u64* yo = (u64*)ysOut;
        u64 C1 = pack2(hh * c1), C2 = pack2(hh * c2), C3 = pack2(hh * c3);
        u64 C4 = pack2(hh * c4), C5 = pack2(hh * c5), CC = pack2(hh * ccur);
        {
            int idx = p0 * 64 + d;
            u64 s = yu[idx];
            fma2(s, C1, k1u[idx]); fma2(s, C2, k2u[idx]); fma2(s, C3, k3u[idx]);
            fma2(s, C4, k4u[idx]); fma2(s, C5, k5u[idx]); fma2(s, CC, kv0);
            yo[idx] = s;
        }
        {
            int idx = (p0 + 1) * 64 + d;
            u64 s = yu[idx];
            fma2(s, C1, k1u[idx]); fma2(s, C2, k2u[idx]); fma2(s, C3, k3u[idx]);
            fma2(s, C4, k4u[idx]); fma2(s, C5, k5u[idx]); fma2(s, CC, kv1);
            yo[idx] = s;
        }
    }
    __syncthreads();
}

__global__ void __launch_bounds__(NT, 1)
node_kernel(const float* __restrict__ ts, const float* __restrict__ y0,
            const float* __restrict__ W0, const float* __restrict__ b0,
            const float* __restrict__ b1, const float* __restrict__ W2,
            const float* __restrict__ b2, float* __restrict__ out) {
    extern __shared__ float sm[];
    const int tid = threadIdx.x;
    const int row0 = blockIdx.x * MT;

    // stage weights into shared
    for (int idx = tid; idx < WID * DIM; idx += NT) {
        int j = idx >> 6, d = idx & 63;
        sm[OFF_W0 + j * 68 + d] = W0[idx];
    }
    for (int idx = tid; idx < DIM * WID; idx += NT) {
        int d = idx >> 8, k = idx & 255;
        sm[OFF_W2 + d * 262 + k] = W2[idx];
    }
    sm[OFF_B0 + tid] = b0[tid];
    sm[OFF_B1 + tid] = b1[tid];
    if (tid < DIM) sm[OFF_B2 + tid] = b2[tid];
    // zero k buffers (combine multiplies unused stages by 0 — must be finite)
    for (int idx = tid; idx < 6144; idx += NT) sm[OFF_K + idx] = 0.0f;

    // load y0 into paired layout; write output slab t=0
    for (int i = tid; i < 512; i += NT) {
        int p = i >> 6, d = i & 63;
        float vlo = y0[(size_t)(row0 + p) * DIM + d];
        float vhi = y0[(size_t)(row0 + p + 8) * DIM + d];
        ((float2*)(sm + OFF_Y))[i] = make_float2(vlo, vhi);
        out[(size_t)(row0 + p) * DIM + d] = vlo;
        out[(size_t)(row0 + p + 8) * DIM + d] = vhi;
    }
    __syncthreads();

    float* yP = sm + OFF_Y;
    float* ysP = sm + OFF_YS;
    float* k1 = sm + OFF_K + 0 * 1024;
    float* k2 = sm + OFF_K + 1 * 1024;
    float* k3 = sm + OFF_K + 2 * 1024;
    float* k4 = sm + OFF_K + 3 * 1024;
    float* k5 = sm + OFF_K + 4 * 1024;
    float* k6 = sm + OFF_K + 5 * 1024;

    const float A21 = 0.2f;
    const float A31 = (float)(3.0 / 40.0), A32 = (float)(9.0 / 40.0);
    const float A41 = (float)(44.0 / 45.0), A42 = (float)(-56.0 / 15.0), A43 = (float)(32.0 / 9.0);
    const float A51 = (float)(19372.0 / 6561.0), A52 = (float)(-25360.0 / 2187.0),
                A53 = (float)(64448.0 / 6561.0), A54 = (float)(-212.0 / 729.0);
    const float A61 = (float)(9017.0 / 3168.0), A62 = (float)(-355.0 / 33.0),
                A63 = (float)(46732.0 / 5247.0), A64 = (float)(49.0 / 176.0),
                A65 = (float)(-5103.0 / 18656.0);
    const float B1 = (float)(35.0 / 384.0), B3 = (float)(500.0 / 1113.0),
                B4 = (float)(125.0 / 192.0), B5 = (float)(-2187.0 / 6784.0),
                B6 = (float)(11.0 / 84.0);

    for (int iv = 0; iv < 31; iv++) {
        float t0 = ts[iv];
        float dtf = ts[iv + 1] - t0;
        float hh = dtf * 0.5f;
        float tc = t0;

        for (int sub = 0; sub < 2; sub++) {
            // stage 1 (reads yP directly), builds ys for stage 2
            vf_eval(sm, g_W1T, tc, tid, yP, k1,
                    hh, 0.f, 0.f, 0.f, 0.f, 0.f, A21, ysP);
            // stage 2
            vf_eval(sm, g_W1T, tc + 0.2f * hh, tid, ysP, k2,
                    hh, A31, 0.f, 0.f, 0.f, 0.f, A32, ysP);
            // stage 3
            vf_eval(sm, g_W1T, tc + 0.3f * hh, tid, ysP, k3,
                    hh, A41, A42, 0.f, 0.f, 0.f, A43, ysP);
            // stage 4
            vf_eval(sm, g_W1T, tc + 0.8f * hh, tid, ysP, k4,
                    hh, A51, A52, A53, 0.f, 0.f, A54, ysP);
            // stage 5
            vf_eval(sm, g_W1T, tc + (float)(8.0 / 9.0) * hh, tid, ysP, k5,
                    hh, A61, A62, A63, A64, 0.f, A65, ysP);
            // stage 6 — final combine writes yP
            vf_eval(sm, g_W1T, tc + hh, tid, ysP, k6,
                    hh, B1, 0.f, B3, B4, B5, B6, yP);
            tc += hh;
        }

        // write output slab t = iv+1 from paired yP
        for (int i = tid; i < 512; i += NT) {
            int p = i >> 6, d = i & 63;
            float2 v = ((float2*)(sm + OFF_Y))[i];
            size_t base = (size_t)(iv + 1) * BD;
            out[base + (size_t)(row0 + p) * DIM + d] = v.x;
            out[base + (size_t)(row0 + p + 8) * DIM + d] = v.y;
        }
        __syncthreads();
    }
}

extern "C" void kernel_launch(void* const* d_in, const int* in_sizes, int n_in,
                              void* d_out, int out_size) {
    const float* ts = (const float*)d_in[0];
    const float* y0 = (const float*)d_in[1];
    const float* W0 = (const float*)d_in[2];
    const float* b0 = (const float*)d_in[3];
    const float* W1 = (const float*)d_in[4];
    const float* b1 = (const float*)d_in[5];
    const float* W2 = (const float*)d_in[6];
    const float* b2 = (const float*)d_in[7];
    float* out = (float*)d_out;

    cudaFuncSetAttribute(node_kernel, cudaFuncAttributeMaxDynamicSharedMemorySize,
                         SMEM_BYTES);

    transpose_w1<<<WID * WID / 256, 256>>>(W1);
    node_kernel<<<NBLK, NT, SMEM_BYTES>>>(ts, y0, W0, b0, b1, W2, b2, out);
}